// round 5
// baseline (speedup 1.0000x reference)
#include <cuda_runtime.h>
#include <cstdint>

#define BB 1024
#define TT 4096
#define SS 8
#define EE 8
#define PHS 64               // scan steps per cp.async phase
#define NPH (TT / PHS)

// Scratch (no cudaMalloc allowed): trajectory states + dt table
__device__ float g_preds[(size_t)BB * TT * SS];   // 134 MB
__device__ float g_dt[TT];

// ---------------------------------------------------------------------------
__global__ void dt_kernel(const float* __restrict__ t) {
    int i = blockIdx.x * blockDim.x + threadIdx.x;
    if (i < TT) g_dt[i] = (i < TT - 1) ? (t[i + 1] - t[i]) : 0.0f;
}

// tanh(x) = 1 - 2/(e^{2x}+1)  via ex2.approx + rcp.approx  (~1 ulp)
__device__ __forceinline__ float fast_tanh(float z) {
    float e; asm("ex2.approx.f32 %0, %1;" : "=f"(e) : "f"(z * 2.8853900817779268f));
    float r; asm("rcp.approx.f32 %0, %1;" : "=f"(r) : "f"(e + 1.0f));
    return fmaf(-2.0f, r, 1.0f);
}

__device__ __forceinline__ void cpa16(float* dst, const float* src) {
    unsigned s = (unsigned)__cvta_generic_to_shared(dst);
    asm volatile("cp.async.cg.shared.global [%0], [%1], 16;" :: "r"(s), "l"(src));
}

// ---------------------------------------------------------------------------
// Sequential Euler scan: one warp per batch element. Lane j owns hidden unit j.
__global__ __launch_bounds__(32)
void scan_kernel(const float* __restrict__ x,    // [B,T,E]
                 const float* __restrict__ y0,   // [B,S]
                 const float* __restrict__ Wr1,  // [S+E, H]
                 const float* __restrict__ br1,  // [H]
                 const float* __restrict__ Wr2,  // [H, S]
                 const float* __restrict__ br2)  // [S]
{
    __shared__ __align__(16) float sx[2][PHS * EE];   // 4 KB double buffer
    const int lane = threadIdx.x;
    const int b = blockIdx.x;
    const float* xb = x + (size_t)b * TT * EE;

    // Register-resident weight slices for hidden unit j = lane
    float wy[8], we[8], w2[8], vb2[8];
#pragma unroll
    for (int k = 0; k < 8; ++k) {
        wy[k]  = Wr1[k * 32 + lane];          // y -> hidden
        we[k]  = Wr1[(8 + k) * 32 + lane];    // exog -> hidden
        w2[k]  = Wr2[lane * 8 + k];           // hidden -> state
        vb2[k] = br2[k];
    }
    const float b1j = br1[lane];

    // Initial state, replicated on every lane
    float y[8];
    {
        const float4* yp = (const float4*)(y0 + (size_t)b * SS);
        float4 A = yp[0], B = yp[1];
        y[0]=A.x; y[1]=A.y; y[2]=A.z; y[3]=A.w;
        y[4]=B.x; y[5]=B.y; y[6]=B.z; y[7]=B.w;
    }

    // Phase staging: 64 steps * 8 floats = 512 floats = 128 x 16B
    auto issue = [&](int ph, int buf) {
        const float* src = xb + (size_t)ph * PHS * EE;
#pragma unroll
        for (int k = 0; k < 4; ++k)
            cpa16(&sx[buf][(lane + 32 * k) * 4], src + (lane + 32 * k) * 4);
        asm volatile("cp.async.commit_group;");
    };

    issue(0, 0);
    float* pp = g_preds + (size_t)b * TT * SS;
    int buf = 0;

    for (int ph = 0; ph < NPH; ++ph) {
        if (ph + 1 < NPH) {
            issue(ph + 1, buf ^ 1);
            asm volatile("cp.async.wait_group 1;");
        } else {
            asm volatile("cp.async.wait_group 0;");
        }
        __syncwarp();
        const float* eb  = sx[buf];
        const float* dtb = g_dt + ph * PHS;

#pragma unroll 2
        for (int i = 0; i < PHS; ++i) {
            // preds[b][t] = state BEFORE this step's update  (preds[0] = y0)
            if (lane == 0) {
                float4* o = (float4*)pp;
                o[0] = make_float4(y[0], y[1], y[2], y[3]);
                o[1] = make_float4(y[4], y[5], y[6], y[7]);
            }
            pp += SS;

            const float4 ea = *(const float4*)(eb + i * 8);
            const float4 ec = *(const float4*)(eb + i * 8 + 4);
            const float dt = dtb[i];

            // z_j = br1[j] + y.Wy[:,j] + e.We[:,j]   (balanced tree)
            float a0 = fmaf(y[1], wy[1], fmaf(y[0], wy[0], b1j));
            float a1 = fmaf(y[3], wy[3], y[2] * wy[2]);
            float a2 = fmaf(y[5], wy[5], y[4] * wy[4]);
            float a3 = fmaf(y[7], wy[7], y[6] * wy[6]);
            float a4 = fmaf(ea.y, we[1], ea.x * we[0]);
            float a5 = fmaf(ea.w, we[3], ea.z * we[2]);
            float a6 = fmaf(ec.y, we[5], ec.x * we[4]);
            float a7 = fmaf(ec.w, we[7], ec.z * we[6]);
            const float z = ((a0 + a1) + (a2 + a3)) + ((a4 + a5) + (a6 + a7));
            const float h = fast_tanh(z);

            // partial rhs_s = h_j * Wr2[j][s], all-reduce over 32 lanes
            float p[8];
#pragma unroll
            for (int s = 0; s < 8; ++s) p[s] = h * w2[s];
#pragma unroll
            for (int m = 16; m; m >>= 1) {
#pragma unroll
                for (int s = 0; s < 8; ++s)
                    p[s] += __shfl_xor_sync(0xffffffffu, p[s], m);
            }
            // Euler update (dt[T-1] = 0 -> final iteration is a no-op)
#pragma unroll
            for (int s = 0; s < 8; ++s) y[s] = fmaf(dt, p[s] + vb2[s], y[s]);
        }
        buf ^= 1;
        __syncwarp();
    }
}

// ---------------------------------------------------------------------------
// Head: out = relu(preds @ W1 + b1) @ W2 + b2  — fully register-resident weights
__global__ __launch_bounds__(256)
void head_kernel(const float* __restrict__ W1, const float* __restrict__ b1,
                 const float* __restrict__ W2, const float* __restrict__ b2,
                 float* __restrict__ out)
{
    float w1[8][10], bb1[10], w2[10][2];
#pragma unroll
    for (int s = 0; s < 8; ++s)
#pragma unroll
        for (int i = 0; i < 10; ++i) w1[s][i] = __ldg(&W1[s * 10 + i]);
#pragma unroll
    for (int i = 0; i < 10; ++i) {
        bb1[i]   = __ldg(&b1[i]);
        w2[i][0] = __ldg(&W2[i * 2 + 0]);
        w2[i][1] = __ldg(&W2[i * 2 + 1]);
    }
    const float c0 = __ldg(&b2[0]), c1 = __ldg(&b2[1]);

    const int nt  = gridDim.x * blockDim.x;
    const int tid = blockIdx.x * blockDim.x + threadIdx.x;
    const int NPOS = BB * TT;

    for (int pos = tid; pos < NPOS; pos += nt) {
        const float4* yp = (const float4*)(g_preds + (size_t)pos * SS);
        const float4 A = yp[0], B = yp[1];
        const float yv[8] = {A.x, A.y, A.z, A.w, B.x, B.y, B.z, B.w};
        float o0 = c0, o1 = c1;
#pragma unroll
        for (int i = 0; i < 10; ++i) {
            float hz = bb1[i];
#pragma unroll
            for (int s = 0; s < 8; ++s) hz = fmaf(yv[s], w1[s][i], hz);
            hz = fmaxf(hz, 0.0f);
            o0 = fmaf(hz, w2[i][0], o0);
            o1 = fmaf(hz, w2[i][1], o1);
        }
        *(float2*)(out + (size_t)pos * 2) = make_float2(o0, o1);
    }
}

// ---------------------------------------------------------------------------
extern "C" void kernel_launch(void* const* d_in, const int* in_sizes, int n_in,
                              void* d_out, int out_size) {
    const float* x   = (const float*)d_in[0];
    const float* t   = (const float*)d_in[1];
    const float* y0  = (const float*)d_in[2];
    const float* Wr1 = (const float*)d_in[3];
    const float* br1 = (const float*)d_in[4];
    const float* Wr2 = (const float*)d_in[5];
    const float* br2 = (const float*)d_in[6];
    const float* W1  = (const float*)d_in[7];
    const float* b1  = (const float*)d_in[8];
    const float* W2  = (const float*)d_in[9];
    const float* b2  = (const float*)d_in[10];
    float* out = (float*)d_out;

    dt_kernel<<<16, 256>>>(t);
    scan_kernel<<<BB, 32>>>(x, y0, Wr1, br1, Wr2, br2);
    head_kernel<<<2048, 256>>>(W1, b1, W2, b2, out);
}

// round 6
// speedup vs baseline: 1.3572x; 1.3572x over previous
#include <cuda_runtime.h>
#include <cstdint>

#define BB 1024
#define TT 4096
#define SS 8
#define EE 8
#define PHS 64              // scan steps per cp.async phase
#define NPH (TT / PHS)
#define CPB 8               // chains per block (2 warps x 4 chains)
#define THREADS 64

// Scratch (no cudaMalloc allowed)
__device__ float g_preds[(size_t)BB * TT * SS];   // 134 MB trajectory
__device__ float g_dt[TT];

using ull = unsigned long long;

// ---------------- f32x2 packed helpers ----------------
__device__ __forceinline__ ull pk2(float lo, float hi) {
    ull r; asm("mov.b64 %0, {%1, %2};" : "=l"(r) : "f"(lo), "f"(hi)); return r;
}
__device__ __forceinline__ void up2(ull a, float& lo, float& hi) {
    asm("mov.b64 {%0, %1}, %2;" : "=f"(lo), "=f"(hi) : "l"(a));
}
__device__ __forceinline__ ull fma2(ull a, ull b, ull c) {
    ull r; asm("fma.rn.f32x2 %0, %1, %2, %3;" : "=l"(r) : "l"(a), "l"(b), "l"(c)); return r;
}
__device__ __forceinline__ ull mul2(ull a, ull b) {
    ull r; asm("mul.rn.f32x2 %0, %1, %2;" : "=l"(r) : "l"(a), "l"(b)); return r;
}
__device__ __forceinline__ ull add2(ull a, ull b) {
    ull r; asm("add.rn.f32x2 %0, %1, %2;" : "=l"(r) : "l"(a), "l"(b)); return r;
}

// tanh(x) = 1 - 2/(e^{2x}+1) via ex2.approx + rcp.approx (~1e-7 rel err)
__device__ __forceinline__ float fast_tanh(float z) {
    float e; asm("ex2.approx.f32 %0, %1;" : "=f"(e) : "f"(z * 2.8853900817779268f));
    float r; asm("rcp.approx.f32 %0, %1;" : "=f"(r) : "f"(e + 1.0f));
    return fmaf(-2.0f, r, 1.0f);
}

__device__ __forceinline__ void cpa16(void* dst, const void* src) {
    unsigned s = (unsigned)__cvta_generic_to_shared(dst);
    asm volatile("cp.async.cg.shared.global [%0], [%1], 16;" :: "r"(s), "l"(src));
}

// ---------------------------------------------------------------------------
__global__ void dt_kernel(const float* __restrict__ t) {
    int i = blockIdx.x * blockDim.x + threadIdx.x;
    if (i < TT) g_dt[i] = (i < TT - 1) ? (t[i + 1] - t[i]) : 0.0f;
}

// ---------------------------------------------------------------------------
// Sequential Euler scan: 8 lanes per chain, 4 chains per warp, 2 warps/block.
// Lane u (=lane&7) owns hidden units j = u + 8m, m = 0..3.
__global__ __launch_bounds__(THREADS, 1)
void scan_kernel(const float* __restrict__ x,    // [B,T,E]
                 const float* __restrict__ y0,   // [B,S]
                 const float* __restrict__ Wr1,  // [S+E, 32]
                 const float* __restrict__ br1,  // [32]
                 const float* __restrict__ Wr2,  // [32, S]
                 const float* __restrict__ br2)  // [S]
{
    __shared__ __align__(16) float sx[2][CPB][PHS * EE];  // 32 KB x-staging
    __shared__ __align__(16) float sdt[2][PHS];           // dt staging

    const int tid  = threadIdx.x;
    const int lane = tid & 31;
    const int w    = tid >> 5;
    const int u    = lane & 7;                         // lane within 8-group
    const int cloc = w * 4 + (lane >> 3);              // chain slot in block
    const int chain = blockIdx.x * CPB + cloc;

    // ---- register-resident weights (packed pairs), units j = u + 8m ----
    ull wy[4][4], we[4][4], w2p[4][4];
    float b1v[4];
#pragma unroll
    for (int m = 0; m < 4; ++m) {
        const int j = u + 8 * m;
#pragma unroll
        for (int k = 0; k < 4; ++k) {
            wy[m][k]  = pk2(Wr1[(2 * k) * 32 + j],     Wr1[(2 * k + 1) * 32 + j]);
            we[m][k]  = pk2(Wr1[(8 + 2 * k) * 32 + j], Wr1[(9 + 2 * k) * 32 + j]);
            w2p[m][k] = pk2(Wr2[j * 8 + 2 * k],        Wr2[j * 8 + 2 * k + 1]);
        }
        b1v[m] = br1[j];
    }
    ull b2p[4];
#pragma unroll
    for (int k = 0; k < 4; ++k) b2p[k] = pk2(br2[2 * k], br2[2 * k + 1]);

    // ---- initial state (replicated per lane, 4 packed pairs) ----
    ull yp[4];
    {
        const float4* q = (const float4*)(y0 + (size_t)chain * SS);
        float4 A = q[0], B = q[1];
        yp[0] = pk2(A.x, A.y); yp[1] = pk2(A.z, A.w);
        yp[2] = pk2(B.x, B.y); yp[3] = pk2(B.z, B.w);
    }

    // ---- phase staging: 8 chains x 512 floats = 1024 x 16B; 16 per thread ----
    auto issue = [&](int ph, int buf) {
#pragma unroll
        for (int q = 0; q < 16; ++q) {
            const int idx = tid + q * 64;         // 0..1023
            const int c   = idx >> 7;             // chain
            const int off = idx & 127;            // 16B chunk within chain
            cpa16(&sx[buf][c][off * 4],
                  x + ((size_t)(blockIdx.x * CPB + c) * TT + (size_t)ph * PHS) * EE + off * 4);
        }
        if (tid < 16) cpa16(&sdt[buf][tid * 4], g_dt + ph * PHS + tid * 4);
        asm volatile("cp.async.commit_group;");
    };

    issue(0, 0);
    asm volatile("cp.async.wait_group 0;");
    __syncthreads();

    float* pp = g_preds + (size_t)chain * TT * SS;
    int buf = 0;

    for (int ph = 0; ph < NPH; ++ph) {
        if (ph + 1 < NPH) {
            issue(ph + 1, buf ^ 1);
            asm volatile("cp.async.wait_group 1;");
        }
        __syncthreads();
        const float* eb  = sx[buf][cloc];
        const float* dtb = sdt[buf];

#pragma unroll 2
        for (int i = 0; i < PHS; ++i) {
            // preds[b][t] = state BEFORE this step's update (preds[0] = y0)
            if (u == 0) {
                float f0, f1, f2, f3, f4, f5, f6, f7;
                up2(yp[0], f0, f1); up2(yp[1], f2, f3);
                up2(yp[2], f4, f5); up2(yp[3], f6, f7);
                float4* o = (float4*)pp;
                o[0] = make_float4(f0, f1, f2, f3);
                o[1] = make_float4(f4, f5, f6, f7);
            }
            pp += SS;

            const float dt = dtb[i];
            const float4 EA = *(const float4*)(eb + i * 8);
            const float4 EB = *(const float4*)(eb + i * 8 + 4);
            const ull e0 = pk2(EA.x, EA.y), e1 = pk2(EA.z, EA.w);
            const ull e2 = pk2(EB.x, EB.y), e3 = pk2(EB.z, EB.w);

            // z_j = br1 + y.Wy + e.We  for 4 owned units; h = tanh(z)
            float h[4];
#pragma unroll
            for (int m = 0; m < 4; ++m) {
                ull a = mul2(yp[0], wy[m][0]);
                ull c = mul2(e0,    we[m][0]);
                a = fma2(yp[1], wy[m][1], a);  c = fma2(e1, we[m][1], c);
                a = fma2(yp[2], wy[m][2], a);  c = fma2(e2, we[m][2], c);
                a = fma2(yp[3], wy[m][3], a);  c = fma2(e3, we[m][3], c);
                const ull s = add2(a, c);
                float lo, hi; up2(s, lo, hi);
                h[m] = fast_tanh(lo + hi + b1v[m]);
            }

            // p[s-pairs] = sum over 4 owned units of h_j * Wr2[j][:]
            ull h2[4];
#pragma unroll
            for (int m = 0; m < 4; ++m) h2[m] = pk2(h[m], h[m]);
            ull p[4];
#pragma unroll
            for (int sp = 0; sp < 4; ++sp) {
                ull t0 = mul2(h2[0], w2p[0][sp]);
                t0 = fma2(h2[1], w2p[1][sp], t0);
                t0 = fma2(h2[2], w2p[2][sp], t0);
                p[sp] = fma2(h2[3], w2p[3][sp], t0);
            }

            // 3-round butterfly all-reduce within the 8-lane group (64-bit shfl)
#pragma unroll
            for (int mask = 1; mask < 8; mask <<= 1) {
#pragma unroll
                for (int sp = 0; sp < 4; ++sp)
                    p[sp] = add2(p[sp], __shfl_xor_sync(0xffffffffu, p[sp], mask));
            }

            // Euler update (dt[T-1]=0 makes the final update a no-op)
            const ull dt2 = pk2(dt, dt);
#pragma unroll
            for (int sp = 0; sp < 4; ++sp)
                yp[sp] = fma2(dt2, add2(p[sp], b2p[sp]), yp[sp]);
        }
        __syncthreads();     // all reads of sx[buf] done before next issue overwrites it
        buf ^= 1;
    }
}

// ---------------------------------------------------------------------------
// Head: out = relu(preds @ W1 + b1) @ W2 + b2 — fully register-resident weights
__global__ __launch_bounds__(256)
void head_kernel(const float* __restrict__ W1, const float* __restrict__ b1,
                 const float* __restrict__ W2, const float* __restrict__ b2,
                 float* __restrict__ out)
{
    float w1[8][10], bb1[10], w2[10][2];
#pragma unroll
    for (int s = 0; s < 8; ++s)
#pragma unroll
        for (int i = 0; i < 10; ++i) w1[s][i] = __ldg(&W1[s * 10 + i]);
#pragma unroll
    for (int i = 0; i < 10; ++i) {
        bb1[i]   = __ldg(&b1[i]);
        w2[i][0] = __ldg(&W2[i * 2 + 0]);
        w2[i][1] = __ldg(&W2[i * 2 + 1]);
    }
    const float c0 = __ldg(&b2[0]), c1 = __ldg(&b2[1]);

    const int nt  = gridDim.x * blockDim.x;
    const int tid = blockIdx.x * blockDim.x + threadIdx.x;
    const int NPOS = BB * TT;

    for (int pos = tid; pos < NPOS; pos += nt) {
        const float4* ypt = (const float4*)(g_preds + (size_t)pos * SS);
        const float4 A = ypt[0], B = ypt[1];
        const float yv[8] = {A.x, A.y, A.z, A.w, B.x, B.y, B.z, B.w};
        float o0 = c0, o1 = c1;
#pragma unroll
        for (int i = 0; i < 10; ++i) {
            float hz = bb1[i];
#pragma unroll
            for (int s = 0; s < 8; ++s) hz = fmaf(yv[s], w1[s][i], hz);
            hz = fmaxf(hz, 0.0f);
            o0 = fmaf(hz, w2[i][0], o0);
            o1 = fmaf(hz, w2[i][1], o1);
        }
        *(float2*)(out + (size_t)pos * 2) = make_float2(o0, o1);
    }
}

// ---------------------------------------------------------------------------
extern "C" void kernel_launch(void* const* d_in, const int* in_sizes, int n_in,
                              void* d_out, int out_size) {
    const float* x   = (const float*)d_in[0];
    const float* t   = (const float*)d_in[1];
    const float* y0  = (const float*)d_in[2];
    const float* Wr1 = (const float*)d_in[3];
    const float* br1 = (const float*)d_in[4];
    const float* Wr2 = (const float*)d_in[5];
    const float* br2 = (const float*)d_in[6];
    const float* W1  = (const float*)d_in[7];
    const float* b1  = (const float*)d_in[8];
    const float* W2  = (const float*)d_in[9];
    const float* b2  = (const float*)d_in[10];
    float* out = (float*)d_out;

    dt_kernel<<<16, 256>>>(t);
    scan_kernel<<<BB / CPB, THREADS>>>(x, y0, Wr1, br1, Wr2, br2);
    head_kernel<<<2048, 256>>>(W1, b1, W2, b2, out);
}